// round 13
// baseline (speedup 1.0000x reference)
#include <cuda_runtime.h>
#include <cstdint>

#define VOCAB 50257
#define DIM   2048
#define RNK   64
#define MT    64             // tokens per CTA
#define NDC   128            // d-columns per chunk
#define NCHUNK (DIM / NDC)   // 16
#define NTHREADS 256
#define BSTRIDE 132          // bounce row stride (floats)
#define BRSTRIDE 68          // raw-B smem row stride (floats), conflict-free

__device__ __forceinline__ uint32_t smem_u32(const void* p) {
    uint32_t a;
    asm("{ .reg .u64 t; cvta.to.shared.u64 t, %1; cvt.u32.u64 %0, t; }" : "=r"(a) : "l"(p));
    return a;
}
__device__ __forceinline__ uint32_t to_tf32(float v) {
    uint32_t r;
    asm("cvt.rna.tf32.f32 %0, %1;" : "=r"(r) : "f"(v));
    return r;
}
__device__ __forceinline__ void cpa16(uint32_t dst, const void* src) {
    asm volatile("cp.async.cg.shared.global [%0], [%1], 16;" :: "r"(dst), "l"(src));
}
__device__ __forceinline__ void pf_l2(const void* p) {
    asm volatile("prefetch.global.L2 [%0];" :: "l"(p));
}
// b operands passed as raw bit patterns (tf32 = top 19 bits of f32)
__device__ __forceinline__ void mma_tf32(float* d, const float4& a, uint32_t bx, uint32_t by) {
    asm volatile(
        "mma.sync.aligned.m16n8k8.row.col.f32.tf32.tf32.f32 "
        "{%0,%1,%2,%3}, {%4,%5,%6,%7}, {%8,%9}, {%0,%1,%2,%3};"
        : "+f"(d[0]), "+f"(d[1]), "+f"(d[2]), "+f"(d[3])
        : "r"(__float_as_uint(a.x)), "r"(__float_as_uint(a.y)),
          "r"(__float_as_uint(a.z)), "r"(__float_as_uint(a.w)),
          "r"(bx), "r"(by));
}
__device__ __forceinline__ void stcs4(float* p, float4 v) {
    asm volatile("st.global.cs.v4.f32 [%0], {%1, %2, %3, %4};"
                 :: "l"(p), "f"(v.x), "f"(v.y), "f"(v.z), "f"(v.w));
}

// ---- single fused kernel: one CTA per 64-token tile (256 CTAs) ----
__global__ void __launch_bounds__(NTHREADS, 2)
lora_main(const int* __restrict__ x,
          const float* __restrict__ W,
          const float* __restrict__ A,
          const float* __restrict__ Bm,
          float* __restrict__ out) {
    extern __shared__ float sm[];
    float* As     = sm;                        // 4096 floats (16 KB): A fragments
    float* Bs     = sm + 4096;                 // 128*68 = 8704 floats (34 KB): raw B, padded
    float* bounce = sm + 4096 + 8704;          // 64*132 = 8448 floats (33 KB)
    int*   toks   = (int*)(sm + 4096 + 8704 + MT * BSTRIDE);

    const int tid   = threadIdx.x;
    const int tBase = blockIdx.x * MT;

    if (tid < MT) toks[tid] = x[tBase + tid];

    // prologue: cp.async raw B rows for chunk 0 into padded smem
    // 128 rows x 64 floats; row = i4>>4, 16B segment = i4&15 (8 per thread)
    {
        uint32_t dst = smem_u32(Bs);
        #pragma unroll
        for (int j = 0; j < 8; ++j) {
            int i4 = j * NTHREADS + tid;
            int row = i4 >> 4, seg = i4 & 15;
            cpa16(dst + row * (BRSTRIDE * 4) + seg * 16,
                  Bm + (size_t)row * RNK + seg * 4);
        }
        asm volatile("cp.async.commit_group;");
    }
    __syncthreads();   // toks visible

    // gather A into mma fragment layout (tf32 RNA-rounded)
    #pragma unroll 4
    for (int i = tid; i < MT * RNK; i += NTHREADS) {
        int t = i & (MT - 1);
        int r = i >> 6;
        uint32_t tv = to_tf32(__ldg(A + (size_t)r * VOCAB + toks[t]));
        int s = r >> 3, kq = r & 7;
        int mtile = t >> 4, row16 = t & 15;
        int grp = row16 & 7, hi = row16 >> 3;
        int lane = grp * 4 + (kq & 3);
        int reg = (kq >> 2) * 2 + hi;
        As[((s * 4 + mtile) * 32 + lane) * 4 + reg] = __uint_as_float(tv);
    }

    const int wid  = tid >> 5;
    const int lane = tid & 31;
    const int mg   = wid >> 2;        // 0..1 : 32-token half  (MMA phase)
    const int ng   = wid & 3;         // 0..3 : 32-col quarter (MMA phase)

    // per-lane raw-B fragment base: n = ng*32 + (lane>>2), k = lane&3
    const float* bline = Bs + (ng * 32 + (lane >> 2)) * BRSTRIDE + (lane & 3);

    // epilogue row ownership: warp `wid` owns rows {i*8 + wid}, i=0..7
    int tokE[8];
    #pragma unroll
    for (int i = 0; i < 8; ++i) tokE[i] = toks[i * 8 + wid];

    // per-lane W L2-prefetch identity: row (lane>>2)*8+wid, 128B segment lane&3
    const int tokP = toks[(lane >> 2) * 8 + wid];
    const float* wPbase = W + (size_t)tokP * DIM + (lane & 3) * 32;
    pf_l2(wPbase);   // chunk 0's W slice

    #pragma unroll 1
    for (int c = 0; c < NCHUNK; ++c) {
        asm volatile("cp.async.wait_group 0;");
        __syncthreads();   // B[c] ready; bounce free (prev epilogue done)

        if (c + 1 < NCHUNK) pf_l2(wPbase + (c + 1) * NDC);

        // ---- MMA: warp tile m32 x n32, K=64; B fragmentized from raw smem ----
        float acc[2][4][4];
        #pragma unroll
        for (int mt = 0; mt < 2; ++mt)
            #pragma unroll
            for (int nt = 0; nt < 4; ++nt)
                #pragma unroll
                for (int k = 0; k < 4; ++k) acc[mt][nt][k] = 0.f;

        #pragma unroll
        for (int s = 0; s < 8; ++s) {
            float4 a[2];
            #pragma unroll
            for (int mt = 0; mt < 2; ++mt)
                a[mt] = *(const float4*)&As[((s * 4 + mg * 2 + mt) * 32 + lane) * 4];
            uint32_t bx[4], by[4];
            #pragma unroll
            for (int nt = 0; nt < 4; ++nt) {
                const float* bp = bline + nt * (8 * BRSTRIDE) + s * 8;
                bx[nt] = __float_as_uint(bp[0]);   // k = s*8 + (lane&3)
                by[nt] = __float_as_uint(bp[4]);   // k + 4
            }
            #pragma unroll
            for (int mt = 0; mt < 2; ++mt)
                #pragma unroll
                for (int nt = 0; nt < 4; ++nt)
                    mma_tf32(acc[mt][nt], a[mt], bx[nt], by[nt]);
        }

        // ---- STS acc -> bounce [row][col], stride 132 ----
        const int grp = lane >> 2;
        const int tig = lane & 3;
        #pragma unroll
        for (int mt = 0; mt < 2; ++mt) {
            int row0 = mg * 32 + mt * 16 + grp;
            #pragma unroll
            for (int nt = 0; nt < 4; ++nt) {
                int col = ng * 32 + nt * 8 + tig * 2;
                *(float2*)&bounce[row0 * BSTRIDE + col] =
                    make_float2(acc[mt][nt][0], acc[mt][nt][1]);
                *(float2*)&bounce[(row0 + 8) * BSTRIDE + col] =
                    make_float2(acc[mt][nt][2], acc[mt][nt][3]);
            }
        }
        __syncthreads();   // bounce ready; Bs fully consumed

        // prefetch raw B[c+1] (overlaps epilogue's DRAM phase)
        if (c + 1 < NCHUNK) {
            const float* src = Bm + (size_t)(c + 1) * NDC * RNK;
            uint32_t dst = smem_u32(Bs);
            #pragma unroll
            for (int j = 0; j < 8; ++j) {
                int i4 = j * NTHREADS + tid;
                int row = i4 >> 4, seg = i4 & 15;
                cpa16(dst + row * (BRSTRIDE * 4) + seg * 16,
                      src + (size_t)row * RNK + seg * 4);
            }
            asm volatile("cp.async.commit_group;");
        }

        // ---- coalesced epilogue: warp owns whole rows; float4 everywhere ----
        const int colB = c * NDC + lane * 4;
        float4 wv[8];
        #pragma unroll
        for (int i = 0; i < 8; ++i)
            wv[i] = __ldg((const float4*)(W + (size_t)tokE[i] * DIM + colB));
        #pragma unroll
        for (int i = 0; i < 8; ++i) {
            int row = i * 8 + wid;
            float4 l = *(const float4*)&bounce[row * BSTRIDE + lane * 4];
            float4 r;
            r.x = fmaf(16.f, l.x, wv[i].x);
            r.y = fmaf(16.f, l.y, wv[i].y);
            r.z = fmaf(16.f, l.z, wv[i].z);
            r.w = fmaf(16.f, l.w, wv[i].w);
            stcs4(out + (size_t)(tBase + row) * DIM + colB, r);
        }
    }
}

extern "C" void kernel_launch(void* const* d_in, const int* in_sizes, int n_in,
                              void* d_out, int out_size) {
    const int*   x  = (const int*)d_in[0];
    const float* W  = (const float*)d_in[1];
    const float* A  = (const float*)d_in[2];
    const float* Bm = (const float*)d_in[3];
    float* out = (float*)d_out;

    const int ntok = in_sizes[0];   // 16384

    const int smemBytes = (4096 + 8704 + MT * BSTRIDE) * 4 + MT * 4;   // 85,248 B
    cudaFuncSetAttribute(lora_main,
                         cudaFuncAttributeMaxDynamicSharedMemorySize, smemBytes);

    lora_main<<<ntok / MT, NTHREADS, smemBytes>>>(x, W, A, Bm, out);
}